// round 17
// baseline (speedup 1.0000x reference)
#include <cuda_runtime.h>
#include <cstdint>

// LIF activation recurrence — cp.async-staged pipeline:
//   keep = (Vm < 1) ? Vm : 0
//   Vm   = relu(x_t + (1 - w_leak) * keep)
//   out  = (Vm > 1) ? 1 : 0
// x: [B=128, T=1000, C=512] f32, w_leak: [C] f32, out: [B, T, C] f32.
//
// R9/R14/R15 showed register-resident prefetch is capped at U~20 by ptxas's
// 64-reg heuristic (it reuses load destination registers, collapsing MLP).
// cp.async tracks in-flight loads in the async-group hardware instead of
// registers: each thread stages its own lane's x into smem 3 chunks (60
// timesteps) ahead. Producer == consumer thread, so cp.async.wait_group is
// the only synchronization needed — no __syncthreads.
// 65536 threads, 64-thread blocks, 20KB smem/block, conflict-free LDS/STS.

#define LIF_B 128
#define LIF_T 1000
#define LIF_C 512
#define LIF_D 20                 // timesteps per chunk (1000 = 50 chunks)
#define LIF_S 4                  // smem stages
#define LIF_NCHUNK (LIF_T / LIF_D)
#define LIF_BLOCK 64

__device__ __forceinline__ void cp_async4(uint32_t dst_smem, const float* src) {
    asm volatile("cp.async.ca.shared.global [%0], [%1], 4;"
                 :: "r"(dst_smem), "l"(src));
}
__device__ __forceinline__ void cp_commit() {
    asm volatile("cp.async.commit_group;");
}
template <int N>
__device__ __forceinline__ void cp_wait() {
    asm volatile("cp.async.wait_group %0;" :: "n"(N));
}

__device__ __forceinline__ float lif_step(float& vm, float wl, float xv) {
    float vk = (vm < 1.0f) ? vm : 0.0f;                       // hard-reset gate
    vm = fmaxf(__fadd_rn(xv, __fmul_rn(wl, vk)), 0.0f);       // relu, unfused mul+add
    return (vm > 1.0f) ? 1.0f : 0.0f;                         // spike
}

__global__ __launch_bounds__(LIF_BLOCK)
void lif_kernel(const float* __restrict__ x,
                const float* __restrict__ w_leak,
                float* __restrict__ out) {
    __shared__ float stg[LIF_S][LIF_D][LIF_BLOCK];   // 20 KB

    const int tid = threadIdx.x;
    const int i = blockIdx.x * LIF_BLOCK + tid;      // 0 .. B*C-1
    const int c = i & (LIF_C - 1);
    const int b = i >> 9;                            // log2(C) = 9

    const float wl = 1.0f - w_leak[c];
    const size_t base = (size_t)b * LIF_T * LIF_C + c;
    const float* xp = x + base;
    float*       op = out + base;

    // smem base address (u32, shared window) for this thread's lane column.
    const uint32_t s0 = (uint32_t)__cvta_generic_to_shared(&stg[0][0][tid]);
    const uint32_t stage_bytes = LIF_D * LIF_BLOCK * 4;   // 5120
    const uint32_t row_bytes   = LIF_BLOCK * 4;           // 256

    // Prime: issue chunks 0..S-2 (3 chunks = 60 timesteps ahead).
    #pragma unroll
    for (int k = 0; k < LIF_S - 1; k++) {
        const float* src = xp + (size_t)k * LIF_D * LIF_C;
        const uint32_t dst = s0 + k * stage_bytes;
        #pragma unroll
        for (int u = 0; u < LIF_D; u++)
            cp_async4(dst + u * row_bytes, src + (size_t)u * LIF_C);
        cp_commit();
    }

    float vm = 0.0f;

    // Main loop: consume chunk k, issue chunk k+3. Groups stay 3 deep.
    #pragma unroll 1
    for (int k = 0; k < LIF_NCHUNK - (LIF_S - 1); k++) {
        // issue chunk k+3 into stage (k+3)%4
        {
            const int kk = k + LIF_S - 1;
            const float* src = xp + (size_t)kk * LIF_D * LIF_C;
            const uint32_t dst = s0 + (uint32_t)(kk & (LIF_S - 1)) * stage_bytes;
            #pragma unroll
            for (int u = 0; u < LIF_D; u++)
                cp_async4(dst + u * row_bytes, src + (size_t)u * LIF_C);
            cp_commit();
        }
        cp_wait<3>();   // chunk k's group is now complete

        const int st = k & (LIF_S - 1);
        float* o = op + (size_t)k * LIF_D * LIF_C;
        #pragma unroll
        for (int u = 0; u < LIF_D; u++)
            __stcs(o + (size_t)u * LIF_C, lif_step(vm, wl, stg[st][u][tid]));
    }

    // Tail: drain all remaining groups, consume last 3 chunks.
    cp_wait<0>();
    #pragma unroll 1
    for (int k = LIF_NCHUNK - (LIF_S - 1); k < LIF_NCHUNK; k++) {
        const int st = k & (LIF_S - 1);
        float* o = op + (size_t)k * LIF_D * LIF_C;
        #pragma unroll
        for (int u = 0; u < LIF_D; u++)
            __stcs(o + (size_t)u * LIF_C, lif_step(vm, wl, stg[st][u][tid]));
    }
}

extern "C" void kernel_launch(void* const* d_in, const int* in_sizes, int n_in,
                              void* d_out, int out_size) {
    const float* x      = (const float*)d_in[0];   // [B, T, C] f32
    const float* w_leak = (const float*)d_in[1];   // [C] f32
    float* out = (float*)d_out;                    // [B, T, C] f32

    const int total = LIF_B * LIF_C;               // 65536 lanes
    lif_kernel<<<total / LIF_BLOCK, LIF_BLOCK>>>(x, w_leak, out);
}